// round 17
// baseline (speedup 1.0000x reference)
#include <cuda_runtime.h>
#include <cuda_fp16.h>
#include <math.h>
#include <stdint.h>

#define B_SZ   2
#define T_SEQ  2048
#define C_EMB  1024
#define NHEAD  16
#define H_DIM  64
#define M_TOT  (B_SZ * T_SEQ)   // 4096

// Scratch (static device arrays) — fp16 storage everywhere
__device__ __half g_xt[(size_t)M_TOT * C_EMB];
__device__ __half g_wqt[(size_t)3 * C_EMB * C_EMB];
__device__ __half g_wpt[(size_t)C_EMB * C_EMB];
__device__ __half g_q[(size_t)B_SZ * NHEAD * T_SEQ * H_DIM];  // [B,H,T,D], pre-scaled 1/8
__device__ __half g_k[(size_t)B_SZ * NHEAD * T_SEQ * H_DIM];  // [B,H,T,D]
__device__ __half g_v[(size_t)B_SZ * NHEAD * H_DIM * T_SEQ];  // [B,H,D,T]  (transposed!)
__device__ __half g_yt[(size_t)M_TOT * C_EMB];                // [B,T,C]
__device__ float  g_cos[T_SEQ * H_DIM];
__device__ float  g_sin[T_SEQ * H_DIM];

// ---------------------------------------------------------------------------
__device__ __forceinline__ uint32_t f2h2(float lo, float hi) {
    __half2 h = __floats2half2_rn(lo, hi);
    return *(uint32_t*)&h;
}
__device__ __forceinline__ void mma_f16(float* c,
                                        uint32_t a0, uint32_t a1, uint32_t a2, uint32_t a3,
                                        uint32_t b0, uint32_t b1) {
    asm volatile(
        "mma.sync.aligned.m16n8k16.row.col.f32.f16.f16.f32 "
        "{%0,%1,%2,%3}, {%4,%5,%6,%7}, {%8,%9}, {%0,%1,%2,%3};"
        : "+f"(c[0]), "+f"(c[1]), "+f"(c[2]), "+f"(c[3])
        : "r"(a0), "r"(a1), "r"(a2), "r"(a3), "r"(b0), "r"(b1));
}
__device__ __forceinline__ void cp16(uint32_t saddr, const void* g) {
    asm volatile("cp.async.cg.shared.global [%0], [%1], 16;" :: "r"(saddr), "l"(g));
}
__device__ __forceinline__ uint32_t ld32h(const __half* p) {
    return *(const uint32_t*)p;
}

// ---------------------------------------------------------------------------
// fp32 -> fp16 convert (vectorized: 4 floats -> 4 halves per thread)
// ---------------------------------------------------------------------------
__global__ void cvt_h_kernel(const float4* __restrict__ src,
                             uint2* __restrict__ dst, int n4) {
    int i = blockIdx.x * blockDim.x + threadIdx.x;
    if (i >= n4) return;
    float4 v = src[i];
    uint2 o;
    o.x = f2h2(v.x, v.y);
    o.y = f2h2(v.z, v.w);
    dst[i] = o;
}

// ---------------------------------------------------------------------------
// RoPE table
// ---------------------------------------------------------------------------
__global__ void rope_table_kernel() {
    int i = blockIdx.x * blockDim.x + threadIdx.x;
    if (i >= T_SEQ * H_DIM) return;
    int t = i >> 6;
    int d = i & 63;
    double f = pow(10000.0, -(double)(d & 31) / 32.0);
    double ang = (double)t * f;
    g_cos[i] = (float)cos(ang);
    g_sin[i] = (float)sin(ang);
}

// ---------------------------------------------------------------------------
// fp16 GEMM mainloop: C[M,N] = A[M,K] * B[N,K]^T, K in halves.
// 128x128 tile, BK=32 halves, 256 threads, warp tile 32x64, 3-stage cp.async.
// ---------------------------------------------------------------------------
#define ALDH 40
#define TILE_H (128 * ALDH)         // 5120 halves
#define STAGE_H (2 * TILE_H)        // 10240 halves
#define GEMM_SMEM_BYTES (3 * STAGE_H * 2)   // 61440 B

__device__ __forceinline__ void gemm_load_stage_h(
    __half* smh, int s, const __half* A, const __half* B,
    int K, int bm, int bn, int k0, int t) {
    __half* base = smh + s * STAGE_H;
#pragma unroll
    for (int c = 0; c < 2; c++) {
        int id = t * 2 + c;            // 0..511
        int row = id >> 2;             // 0..127
        int ko = (id & 3) * 8;         // 0,8,16,24 halves
        uint32_t so = (uint32_t)__cvta_generic_to_shared(base + row * ALDH + ko);
        cp16(so,              A + (size_t)(bm + row) * K + k0 + ko);
        cp16(so + TILE_H * 2, B + (size_t)(bn + row) * K + k0 + ko);
    }
    asm volatile("cp.async.commit_group;");
}

#define GEMM_MAINLOOP_H(A, B, K, bm, bn)                                       \
    int nkt = (K) / 32;                                                        \
    gemm_load_stage_h(smh, 0, A, B, K, bm, bn, 0, t);                          \
    gemm_load_stage_h(smh, 1, A, B, K, bm, bn, 32, t);                         \
    for (int kt = 0; kt < nkt; kt++) {                                         \
        asm volatile("cp.async.wait_group 1;");                                \
        __syncthreads();                                                       \
        if (kt + 2 < nkt)                                                      \
            gemm_load_stage_h(smh, (kt + 2) % 3, A, B, K, bm, bn,              \
                              (kt + 2) * 32, t);                               \
        else                                                                   \
            asm volatile("cp.async.commit_group;");                            \
        __half* As = smh + (kt % 3) * STAGE_H;                                 \
        __half* Bs = As + TILE_H;                                              \
        _Pragma("unroll")                                                      \
        for (int ks = 0; ks < 2; ks++) {                                       \
            int kb = ks * 16;                                                  \
            uint32_t ah[2][4];                                                 \
            _Pragma("unroll")                                                  \
            for (int mt = 0; mt < 2; mt++) {                                   \
                int row = mw + mt * 16 + gid;                                  \
                ah[mt][0] = ld32h(As + row * ALDH + kb + 2 * tig);             \
                ah[mt][1] = ld32h(As + (row + 8) * ALDH + kb + 2 * tig);       \
                ah[mt][2] = ld32h(As + row * ALDH + kb + 2 * tig + 8);         \
                ah[mt][3] = ld32h(As + (row + 8) * ALDH + kb + 2 * tig + 8);   \
            }                                                                  \
            uint32_t bh[8][2];                                                 \
            _Pragma("unroll")                                                  \
            for (int nt = 0; nt < 8; nt++) {                                   \
                int n = nw + nt * 8 + gid;                                     \
                bh[nt][0] = ld32h(Bs + n * ALDH + kb + 2 * tig);               \
                bh[nt][1] = ld32h(Bs + n * ALDH + kb + 2 * tig + 8);           \
            }                                                                  \
            _Pragma("unroll")                                                  \
            for (int mt = 0; mt < 2; mt++)                                     \
                _Pragma("unroll")                                              \
                for (int nt = 0; nt < 8; nt++)                                 \
                    mma_f16(c[mt][nt], ah[mt][0], ah[mt][1], ah[mt][2],        \
                            ah[mt][3], bh[nt][0], bh[nt][1]);                  \
        }                                                                      \
    }

// ---------------------------------------------------------------------------
// Proj GEMM: fp16 inputs, fp32 output.
// ---------------------------------------------------------------------------
__global__ __launch_bounds__(256)
void sgemm_f16(const __half* __restrict__ A, const __half* __restrict__ B,
               float* __restrict__ Cm, int M, int N, int K) {
    extern __shared__ __align__(16) __half smh[];
    int t = threadIdx.x;
    int lane = t & 31, w = t >> 5;
    int gid = lane >> 2, tig = lane & 3;
    int mw = (w & 3) * 32;
    int nw = (w >> 2) * 64;
    int bm = blockIdx.y * 128, bn = blockIdx.x * 128;
    float c[2][8][4] = {};

    GEMM_MAINLOOP_H(A, B, K, bm, bn)

#pragma unroll
    for (int mt = 0; mt < 2; mt++) {
        int row = bm + mw + mt * 16 + gid;
#pragma unroll
        for (int nt = 0; nt < 8; nt++) {
            int col = bn + nw + nt * 8 + 2 * tig;
            *(float2*)&Cm[(size_t)row * N + col] =
                make_float2(c[mt][nt][0], c[mt][nt][1]);
            *(float2*)&Cm[(size_t)(row + 8) * N + col] =
                make_float2(c[mt][nt][2], c[mt][nt][3]);
        }
    }
}

// ---------------------------------------------------------------------------
// QKV GEMM with fused RoPE epilogue -> g_q (scaled 1/8), g_k [B,H,T,D] and
// g_v TRANSPOSED [B,H,D,T], all fp16. Rotation partner c[mt][nt^4][j] in-thread.
// ---------------------------------------------------------------------------
__global__ __launch_bounds__(256)
void sgemm_qkv_rope(const __half* __restrict__ A, const __half* __restrict__ B,
                    int M, int N, int K) {
    extern __shared__ __align__(16) __half smh[];
    int t = threadIdx.x;
    int lane = t & 31, w = t >> 5;
    int gid = lane >> 2, tig = lane & 3;
    int mw = (w & 3) * 32;
    int nw = (w >> 2) * 64;
    int bm = blockIdx.y * 128, bn = blockIdx.x * 128;
    float c[2][8][4] = {};

    GEMM_MAINLOOP_H(A, B, K, bm, bn)

    int colbase = bn + nw;               // 64-aligned
    int sec = colbase >> 10;             // 0=q, 1=k, 2=v
    int h   = (colbase & 1023) >> 6;

#pragma unroll
    for (int mt = 0; mt < 2; mt++) {
        int row0 = bm + mw + mt * 16 + gid;
        int row1 = row0 + 8;
        int b0 = row0 >> 11, t0 = row0 & 2047;
        int t1 = row1 & 2047;            // same batch as row0

        if (sec == 2) {
            size_t vb = (size_t)(b0 * NHEAD + h) * H_DIM * T_SEQ;
#pragma unroll
            for (int nt = 0; nt < 8; nt++) {
                int d = nt * 8 + 2 * tig;
                g_v[vb + (size_t)d * T_SEQ + t0]       = __float2half_rn(c[mt][nt][0]);
                g_v[vb + (size_t)(d + 1) * T_SEQ + t0] = __float2half_rn(c[mt][nt][1]);
                g_v[vb + (size_t)d * T_SEQ + t1]       = __float2half_rn(c[mt][nt][2]);
                g_v[vb + (size_t)(d + 1) * T_SEQ + t1] = __float2half_rn(c[mt][nt][3]);
            }
        } else {
            __half* dst = (sec == 0) ? g_q : g_k;
            size_t ob0 = ((size_t)(b0 * NHEAD + h) * T_SEQ + t0) * H_DIM;
            size_t ob1 = ((size_t)(b0 * NHEAD + h) * T_SEQ + t1) * H_DIM;
#pragma unroll
            for (int nt = 0; nt < 8; nt++) {
                int d = nt * 8 + 2 * tig;
                float sgn = (nt < 4) ? -1.f : 1.f;
                int po = nt ^ 4;
                float cs00 = g_cos[t0 * 64 + d], cs01 = g_cos[t0 * 64 + d + 1];
                float sn00 = g_sin[t0 * 64 + d], sn01 = g_sin[t0 * 64 + d + 1];
                float cs10 = g_cos[t1 * 64 + d], cs11 = g_cos[t1 * 64 + d + 1];
                float sn10 = g_sin[t1 * 64 + d], sn11 = g_sin[t1 * 64 + d + 1];
                float v0 = c[mt][nt][0] * cs00 + sgn * c[mt][po][0] * sn00;
                float v1 = c[mt][nt][1] * cs01 + sgn * c[mt][po][1] * sn01;
                float v2 = c[mt][nt][2] * cs10 + sgn * c[mt][po][2] * sn10;
                float v3 = c[mt][nt][3] * cs11 + sgn * c[mt][po][3] * sn11;
                if (sec == 0) {
                    v0 *= 0.125f; v1 *= 0.125f; v2 *= 0.125f; v3 *= 0.125f;
                }
                *(uint32_t*)&dst[ob0 + d] = f2h2(v0, v1);
                *(uint32_t*)&dst[ob1 + d] = f2h2(v2, v3);
            }
        }
    }
}

// ---------------------------------------------------------------------------
// Flash attention (causal), fp16 m16n8k16 mma, 3-stage cp.async K/V pipeline.
// Block 256 threads (8 warps), 128 Q rows (16/warp), 64-key tiles.
// P C-fragments map DIRECTLY onto fp16 A-fragments (no shfl, no smem).
// K smem [n][k]; V smem [d][t] (gmem pre-transposed).
// ---------------------------------------------------------------------------
#define KLDH 72
#define KT_H (64 * KLDH)                  // 4608 halves (9216 B)
#define STAGE_ATTN_H (2 * KT_H)           // K tile + V tile per stage
#define ATTN_SMEM_BYTES (3 * STAGE_ATTN_H * 2)   // 55296 B

__device__ __forceinline__ void attn_load_tile(
    __half* stage, const __half* Kb, const __half* Vt, int kt, int t) {
    __half* Ksm = stage;
    __half* Vsm = stage + KT_H;
#pragma unroll
    for (int c = 0; c < 2; c++) {
        int id = t * 2 + c;            // 0..511
        int row = id >> 3;             // 0..63
        int ko = (id & 7) * 8;         // 0..56 halves
        uint32_t ks = (uint32_t)__cvta_generic_to_shared(Ksm + row * KLDH + ko);
        uint32_t vs = (uint32_t)__cvta_generic_to_shared(Vsm + row * KLDH + ko);
        cp16(ks, Kb + ((size_t)kt * 64 + row) * H_DIM + ko);
        cp16(vs, Vt + (size_t)row * T_SEQ + kt * 64 + ko);
    }
    asm volatile("cp.async.commit_group;");
}

__global__ __launch_bounds__(256)
void attn_mma_kernel(const __half* __restrict__ Q, const __half* __restrict__ Kg,
                     const __half* __restrict__ Vg, __half* __restrict__ Yt) {
    extern __shared__ __align__(16) __half smh[];

    int t = threadIdx.x;
    int lane = t & 31, w = t >> 5;
    int gid = lane >> 2, tig = lane & 3;
    int qt = gridDim.x - 1 - blockIdx.x;   // heavy-first
    int bh = blockIdx.y;
    int wrow = w * 16;

    const __half* Qb = Q  + (size_t)bh * T_SEQ * H_DIM;
    const __half* Kb = Kg + (size_t)bh * T_SEQ * H_DIM;
    const __half* Vt = Vg + (size_t)bh * H_DIM * T_SEQ;

    int r0g = qt * 128 + wrow + gid;
    int r1g = r0g + 8;

    // Q fragments: 4 k16-chunks x 4 regs (half2), direct from gmem
    uint32_t qa[4][4];
#pragma unroll
    for (int kc = 0; kc < 4; kc++) {
        const __half* q0 = Qb + (size_t)r0g * H_DIM + kc * 16 + 2 * tig;
        const __half* q1 = Qb + (size_t)r1g * H_DIM + kc * 16 + 2 * tig;
        qa[kc][0] = ld32h(q0);
        qa[kc][1] = ld32h(q1);
        qa[kc][2] = ld32h(q0 + 8);
        qa[kc][3] = ld32h(q1 + 8);
    }

    float o[8][4] = {};
    float m0 = -INFINITY, m1 = -INFINITY;
    float l0 = 0.f, l1 = 0.f;

    int ktmax = 2 * qt + 1;
    attn_load_tile(smh, Kb, Vt, 0, t);
    if (1 <= ktmax) attn_load_tile(smh + STAGE_ATTN_H, Kb, Vt, 1, t);
    else            asm volatile("cp.async.commit_group;");

    for (int kt = 0; kt <= ktmax; kt++) {
        asm volatile("cp.async.wait_group 1;");
        __syncthreads();
        if (kt + 2 <= ktmax)
            attn_load_tile(smh + ((kt + 2) % 3) * STAGE_ATTN_H, Kb, Vt, kt + 2, t);
        else
            asm volatile("cp.async.commit_group;");
        __half* Ksm = smh + (kt % 3) * STAGE_ATTN_H;
        __half* Vsm = Ksm + KT_H;

        // S = Q K^T (scale folded into Q)
        float s[8][4] = {};
#pragma unroll
        for (int kc = 0; kc < 4; kc++) {
            int kb = kc * 16;
#pragma unroll
            for (int nt = 0; nt < 8; nt++) {
                int n = nt * 8 + gid;
                uint32_t b0 = ld32h(Ksm + n * KLDH + kb + 2 * tig);
                uint32_t b1 = ld32h(Ksm + n * KLDH + kb + 2 * tig + 8);
                mma_f16(s[nt], qa[kc][0], qa[kc][1], qa[kc][2], qa[kc][3], b0, b1);
            }
        }

        if (kt * 64 + 63 > qt * 128 + wrow) {
#pragma unroll
            for (int nt = 0; nt < 8; nt++) {
                int col = kt * 64 + nt * 8 + 2 * tig;
                if (col > r0g)     s[nt][0] = -INFINITY;
                if (col + 1 > r0g) s[nt][1] = -INFINITY;
                if (col > r1g)     s[nt][2] = -INFINITY;
                if (col + 1 > r1g) s[nt][3] = -INFINITY;
            }
        }

        float mt0 = -INFINITY, mt1 = -INFINITY;
#pragma unroll
        for (int nt = 0; nt < 8; nt++) {
            mt0 = fmaxf(mt0, fmaxf(s[nt][0], s[nt][1]));
            mt1 = fmaxf(mt1, fmaxf(s[nt][2], s[nt][3]));
        }
        mt0 = fmaxf(mt0, __shfl_xor_sync(0xffffffffu, mt0, 1));
        mt0 = fmaxf(mt0, __shfl_xor_sync(0xffffffffu, mt0, 2));
        mt1 = fmaxf(mt1, __shfl_xor_sync(0xffffffffu, mt1, 1));
        mt1 = fmaxf(mt1, __shfl_xor_sync(0xffffffffu, mt1, 2));

        float mn0 = fmaxf(m0, mt0), mn1 = fmaxf(m1, mt1);
        float al0 = __expf(m0 - mn0), al1 = __expf(m1 - mn1);
        m0 = mn0; m1 = mn1;

        float ls0 = 0.f, ls1 = 0.f;
#pragma unroll
        for (int nt = 0; nt < 8; nt++) {
            s[nt][0] = __expf(s[nt][0] - mn0);
            s[nt][1] = __expf(s[nt][1] - mn0);
            s[nt][2] = __expf(s[nt][2] - mn1);
            s[nt][3] = __expf(s[nt][3] - mn1);
            ls0 += s[nt][0] + s[nt][1];
            ls1 += s[nt][2] + s[nt][3];
        }
        ls0 += __shfl_xor_sync(0xffffffffu, ls0, 1);
        ls0 += __shfl_xor_sync(0xffffffffu, ls0, 2);
        ls1 += __shfl_xor_sync(0xffffffffu, ls1, 1);
        ls1 += __shfl_xor_sync(0xffffffffu, ls1, 2);
        l0 = l0 * al0 + ls0;
        l1 = l1 * al1 + ls1;

#pragma unroll
        for (int nt = 0; nt < 8; nt++) {
            o[nt][0] *= al0; o[nt][1] *= al0;
            o[nt][2] *= al1; o[nt][3] *= al1;
        }

        // O += P * V ; P C-frag == fp16 A-frag layout (direct pack, no shfl)
#pragma unroll
        for (int kc = 0; kc < 4; kc++) {
            uint32_t pa0 = f2h2(s[2 * kc][0],     s[2 * kc][1]);
            uint32_t pa1 = f2h2(s[2 * kc][2],     s[2 * kc][3]);
            uint32_t pa2 = f2h2(s[2 * kc + 1][0], s[2 * kc + 1][1]);
            uint32_t pa3 = f2h2(s[2 * kc + 1][2], s[2 * kc + 1][3]);
            int kb = kc * 16;
#pragma unroll
            for (int nt = 0; nt < 8; nt++) {
                int d = nt * 8 + gid;
                uint32_t b0 = ld32h(Vsm + d * KLDH + kb + 2 * tig);
                uint32_t b1 = ld32h(Vsm + d * KLDH + kb + 2 * tig + 8);
                mma_f16(o[nt], pa0, pa1, pa2, pa3, b0, b1);
            }
        }
    }

    // finalize: divide by l, write fp16 into Yt [B,T,C]
    float inv0 = 1.f / l0, inv1 = 1.f / l1;
    int b = bh >> 4, h = bh & 15;
    size_t off0 = ((size_t)b * T_SEQ + r0g) * C_EMB + h * 64;
    size_t off1 = ((size_t)b * T_SEQ + r1g) * C_EMB + h * 64;
#pragma unroll
    for (int nt = 0; nt < 8; nt++) {
        int col = nt * 8 + 2 * tig;
        *(uint32_t*)&Yt[off0 + col] = f2h2(o[nt][0] * inv0, o[nt][1] * inv0);
        *(uint32_t*)&Yt[off1 + col] = f2h2(o[nt][2] * inv1, o[nt][3] * inv1);
    }
}

// ---------------------------------------------------------------------------
extern "C" void kernel_launch(void* const* d_in, const int* in_sizes, int n_in,
                              void* d_out, int out_size) {
    const float* x      = (const float*)d_in[0];
    const float* w_qkv  = (const float*)d_in[1];
    const float* w_proj = (const float*)d_in[2];
    float* out = (float*)d_out;

    __half *p_xt, *p_wqt, *p_wpt, *p_q, *p_k, *p_v, *p_yt;
    cudaGetSymbolAddress((void**)&p_xt, g_xt);
    cudaGetSymbolAddress((void**)&p_wqt, g_wqt);
    cudaGetSymbolAddress((void**)&p_wpt, g_wpt);
    cudaGetSymbolAddress((void**)&p_q, g_q);
    cudaGetSymbolAddress((void**)&p_k, g_k);
    cudaGetSymbolAddress((void**)&p_v, g_v);
    cudaGetSymbolAddress((void**)&p_yt, g_yt);

    // RoPE tables + fp16 pre-conversion
    rope_table_kernel<<<(T_SEQ * H_DIM + 255) / 256, 256>>>();
    cvt_h_kernel<<<(M_TOT * C_EMB / 4 + 255) / 256, 256>>>(
        (const float4*)x, (uint2*)p_xt, M_TOT * C_EMB / 4);
    cvt_h_kernel<<<(3 * C_EMB * C_EMB / 4 + 255) / 256, 256>>>(
        (const float4*)w_qkv, (uint2*)p_wqt, 3 * C_EMB * C_EMB / 4);
    cvt_h_kernel<<<(C_EMB * C_EMB / 4 + 255) / 256, 256>>>(
        (const float4*)w_proj, (uint2*)p_wpt, C_EMB * C_EMB / 4);

    cudaFuncSetAttribute(sgemm_qkv_rope,
                         cudaFuncAttributeMaxDynamicSharedMemorySize, GEMM_SMEM_BYTES);
    cudaFuncSetAttribute(sgemm_f16,
                         cudaFuncAttributeMaxDynamicSharedMemorySize, GEMM_SMEM_BYTES);

    // QKV GEMM with fused RoPE epilogue -> g_q/g_k/g_v
    sgemm_qkv_rope<<<dim3((3 * C_EMB) / 128, M_TOT / 128), 256, GEMM_SMEM_BYTES>>>(
        p_xt, p_wqt, M_TOT, 3 * C_EMB, C_EMB);

    // Flash attention (fp16, 3-stage pipeline)
    cudaFuncSetAttribute(attn_mma_kernel,
                         cudaFuncAttributeMaxDynamicSharedMemorySize, ATTN_SMEM_BYTES);
    attn_mma_kernel<<<dim3(T_SEQ / 128, B_SZ * NHEAD), 256, ATTN_SMEM_BYTES>>>(
        p_q, p_k, p_v, p_yt);

    // Proj GEMM: fp16 in, fp32 out
    sgemm_f16<<<dim3(C_EMB / 128, M_TOT / 128), 256, GEMM_SMEM_BYTES>>>(
        p_yt, p_wpt, out, M_TOT, C_EMB, C_EMB);
}